// round 6
// baseline (speedup 1.0000x reference)
#include <cuda_runtime.h>
#include <cstdint>

#define BB   16
#define XS_  256
#define NN   500000
#define LATD 8
#define NKX  129   // XS/2 + 1

// ---- static scratch (no allocs allowed) ----
__device__ float g_img [BB * XS_ * XS_];
__device__ float g_fre [BB * XS_ * NKX];
__device__ float g_fim [BB * XS_ * NKX];
__device__ float g_h   [BB * LATD];
__device__ float g_pose[BB * 8];

// Gaussian taps (match jnp: exp(-0.5 d^2) normalized, f32)
__device__ __forceinline__ float gwt(int d) {
    const float w0 = 0.00443305f;   // |d|=3
    const float w1 = 0.05400558f;   // |d|=2
    const float w2 = 0.24203623f;   // |d|=1
    const float w3 = 0.39905033f;   // d=0
    int a = d < 0 ? -d : d;
    return a == 0 ? w3 : (a == 1 ? w2 : (a == 2 ? w1 : w0));
}

// ============================================================
// 0) zero image + pose/MLP prep (merged; disjoint arrays, no sync needed)
// ============================================================
__global__ void k_zero_prep(const float* __restrict__ rows,
                            const float* __restrict__ shifts,
                            const float* __restrict__ latent,
                            const float* __restrict__ W0, const float* __restrict__ b0,
                            const float* __restrict__ W1, const float* __restrict__ b1,
                            const float* __restrict__ W2, const float* __restrict__ b2,
                            const float* __restrict__ W3, const float* __restrict__ b3) {
    int i = blockIdx.x * blockDim.x + threadIdx.x;
    if (i < BB * XS_ * XS_) g_img[i] = 0.0f;

    if (blockIdx.x == 0 && threadIdx.x < BB) {
        int b = threadIdx.x;
        float rot = rows[b*3+0], tilt = rows[b*3+1], psi = rows[b*3+2];
        float ca = cosf(rot),  sa = sinf(rot);
        float cb = cosf(tilt), sb = sinf(tilt);
        float cg = cosf(psi),  sg = sinf(psi);

        float cgcb  = __fmul_rn(cg, cb);
        float nsgcb = __fmul_rn(-sg, cb);

        float r00 = __fsub_rn(__fmul_rn(cgcb, ca), __fmul_rn(sg, sa));
        float r01 = __fadd_rn(__fmul_rn(cgcb, sa), __fmul_rn(sg, ca));
        float r02 = -__fmul_rn(cg, sb);
        float r10 = __fsub_rn(__fmul_rn(nsgcb, ca), __fmul_rn(cg, sa));
        float r11 = __fadd_rn(__fmul_rn(nsgcb, sa), __fmul_rn(cg, ca));
        float r12 = __fmul_rn(sg, sb);

        g_pose[b*8+0] = r00;
        g_pose[b*8+1] = r01;
        g_pose[b*8+2] = r02;
        g_pose[b*8+3] = r10;
        g_pose[b*8+4] = r11;
        g_pose[b*8+5] = r12;
        g_pose[b*8+6] = shifts[b*2+0];
        g_pose[b*8+7] = shifts[b*2+1];

        float lat[LATD];
        #pragma unroll
        for (int ii = 0; ii < LATD; ii++) lat[ii] = latent[b*LATD+ii];

        float h[LATD], z[LATD];
        #pragma unroll
        for (int j = 0; j < LATD; j++) {
            float acc = 0.0f;
            #pragma unroll
            for (int ii = 0; ii < LATD; ii++) acc = fmaf(lat[ii], W0[ii*LATD+j], acc);
            acc = __fadd_rn(acc, b0[j]);
            h[j] = sinf(__fmul_rn(30.0f, acc));
        }
        const float* Ws[3] = {W1, W2, W3};
        const float* bs[3] = {b1, b2, b3};
        for (int L = 0; L < 3; L++) {
            #pragma unroll
            for (int j = 0; j < LATD; j++) {
                float acc = 0.0f;
                #pragma unroll
                for (int ii = 0; ii < LATD; ii++) acc = fmaf(h[ii], Ws[L][ii*LATD+j], acc);
                acc = __fadd_rn(acc, bs[L][j]);
                z[j] = sinf(acc);
            }
            #pragma unroll
            for (int j = 0; j < LATD; j++) h[j] = __fadd_rn(h[j], z[j]);
        }
        #pragma unroll
        for (int j = 0; j < LATD; j++) g_h[b*LATD+j] = h[j];
    }
}

// ============================================================
// 1) rotation + decode + scatter-add (bit-identical arithmetic)
// ============================================================
__global__ void __launch_bounds__(256)
k_scatter(const float* __restrict__ coords,
          const float* __restrict__ values,
          const float* __restrict__ Wd,
          const float* __restrict__ bd) {
    __shared__ float4 sh[BB * 2];   // h packed
    __shared__ float4 sp[BB * 2];   // pose packed
    int t = threadIdx.x;
    if (t < BB * 2) {
        const float4* gh = (const float4*)g_h;
        const float4* gp = (const float4*)g_pose;
        sh[t] = gh[t];
        sp[t] = gp[t];
    }
    __syncthreads();

    int n = blockIdx.x * blockDim.x + t;
    if (n >= NN) return;

    float x  = coords[3*n+0];
    float y  = coords[3*n+1];
    float zc = coords[3*n+2];
    float w[LATD];
    #pragma unroll
    for (int l = 0; l < LATD; l++) w[l] = Wd[l*NN + n];
    float vn  = values[n];
    float bdn = bd[n];

    #pragma unroll
    for (int b = 0; b < BB; b++) {
        float4 pa = sp[b*2+0];     // r00 r01 r02 r10
        float4 pb = sp[b*2+1];     // r11 r12 sx  sy
        float dx = fmaf(pa.x, x, 0.0f);
        dx = fmaf(pa.y, y,  dx);
        dx = fmaf(pa.z, zc, dx);
        float dy = fmaf(pa.w, x, 0.0f);
        dy = fmaf(pb.x, y,  dy);
        dy = fmaf(pb.y, zc, dy);
        float pxf = rintf(__fadd_rn(__fadd_rn(dx, pb.z), 128.0f));
        float pyf = rintf(__fadd_rn(__fadd_rn(dy, pb.w), 128.0f));
        pxf = fminf(fmaxf(pxf, 0.0f), 255.0f);
        pyf = fminf(fmaxf(pyf, 0.0f), 255.0f);
        int px = (int)pxf;
        int py = (int)pyf;

        float4 h0 = sh[b*2+0];
        float4 h1 = sh[b*2+1];
        float acc = 0.0f;
        acc = fmaf(h0.x, w[0], acc);
        acc = fmaf(h0.y, w[1], acc);
        acc = fmaf(h0.z, w[2], acc);
        acc = fmaf(h0.w, w[3], acc);
        acc = fmaf(h1.x, w[4], acc);
        acc = fmaf(h1.y, w[5], acc);
        acc = fmaf(h1.z, w[6], acc);
        acc = fmaf(h1.w, w[7], acc);
        float v = __fadd_rn(vn, __fadd_rn(acc, bdn));
        atomicAdd(&g_img[(b << 16) + (py << 8) + px], v);
    }
}

// ============================================================
// 256-point radix-2 DIT FFT, shared twiddle table, 128 threads.
// Input bit-reversed, output natural order.
// ============================================================
__device__ __forceinline__ void fft256_tw(float* sre, float* sim,
                                          const float2* tw, int t, bool inv) {
    #pragma unroll
    for (int s = 1; s <= 8; s++) {
        int len  = 1 << s;
        int half = len >> 1;
        int grp = t >> (s - 1);
        int j   = t & (half - 1);
        int i0  = grp * len + j;
        int i1  = i0 + half;
        float2 w = tw[j << (8 - s)];
        float wr = w.x;
        float wi = inv ? -w.y : w.y;
        float xr = sre[i1], xi = sim[i1];
        float vr = xr*wr - xi*wi;
        float vi = xr*wi + xi*wr;
        float ur = sre[i0], ui = sim[i0];
        sre[i0] = ur + vr;  sim[i0] = ui + vi;
        sre[i1] = ur - vr;  sim[i1] = ui - vi;
        __syncthreads();
    }
}

__device__ __forceinline__ int brev8(int i) { return (int)(__brev((unsigned)i) >> 24); }

__device__ __forceinline__ void init_tw(float2* tw, int t) {
    float s, c;
    sincospif((float)t * (1.0f / 128.0f), &s, &c);
    tw[t] = make_float2(c, -s);
}

// 2) row-wise: horizontal blur (spatial, zero-padded SAME) + rfft
//    g_img rows -> g_fre/g_fim [row][0..128]
__global__ void __launch_bounds__(128) k_rfft_row() {
    __shared__ float raw[256];
    __shared__ float sre[256], sim[256];
    __shared__ float2 tw[128];
    int t = threadIdx.x;
    init_tw(tw, t);
    int row = blockIdx.x;                 // b*256 + y
    const float* src = &g_img[row * XS_];
    raw[t]       = src[t];
    raw[t + 128] = src[t + 128];
    __syncthreads();

    // blurred value at bit-reversed positions -> FFT input
    #pragma unroll
    for (int q = 0; q < 2; q++) {
        int p = t + q * 128;
        int i = brev8(p);
        float acc = 0.0f;
        #pragma unroll
        for (int d = -3; d <= 3; d++) {
            int xx = i + d;
            if (xx >= 0 && xx < XS_) acc += gwt(d) * raw[xx];
        }
        sre[p] = acc;
        sim[p] = 0.0f;
    }
    __syncthreads();
    fft256_tw(sre, sim, tw, t, false);
    float* dre = &g_fre[row * NKX];
    float* dim = &g_fim[row * NKX];
    dre[t] = sre[t];  dim[t] = sim[t];
    if (t == 0) { dre[128] = sre[128]; dim[128] = sim[128]; }
}

// 3) column pass: vertical blur of row-spectra (linearity, zero-padded SAME),
//    column FFT over y, CTF multiply, inverse column FFT.
__global__ void __launch_bounds__(128) k_col_ctf(const float* __restrict__ ctf) {
    __shared__ float rre[256], rim[256];    // raw column, natural y order
    __shared__ float sre[256], sim[256];    // FFT workspace
    __shared__ float2 tw[128];
    int t  = threadIdx.x;
    init_tw(tw, t);
    int b  = blockIdx.x / NKX;
    int kx = blockIdx.x % NKX;
    int base = b * XS_ * NKX + kx;

    rre[t]       = g_fre[base + t * NKX];        rim[t]       = g_fim[base + t * NKX];
    rre[t + 128] = g_fre[base + (t+128) * NKX];  rim[t + 128] = g_fim[base + (t+128) * NKX];
    __syncthreads();

    // vertical 7-tap blur of spectra over y, written to bit-reversed positions
    #pragma unroll
    for (int q = 0; q < 2; q++) {
        int p = t + q * 128;
        int y = brev8(p);
        float ar = 0.0f, ai = 0.0f;
        #pragma unroll
        for (int d = -3; d <= 3; d++) {
            int yy = y + d;
            if (yy >= 0 && yy < XS_) {
                float g = gwt(d);
                ar += g * rre[yy];
                ai += g * rim[yy];
            }
        }
        sre[p] = ar;
        sim[p] = ai;
    }
    __syncthreads();
    fft256_tw(sre, sim, tw, t, false);

    int r0 = brev8(t), r1 = brev8(t + 128);
    const float* cp = &ctf[base];
    float c0 = cp[t * NKX];
    float c1 = cp[(t + 128) * NKX];
    float ar = sre[t]       * c0, ai = sim[t]       * c0;
    float br = sre[t + 128] * c1, bi = sim[t + 128] * c1;
    __syncthreads();
    sre[r0] = ar;  sim[r0] = ai;
    sre[r1] = br;  sim[r1] = bi;
    __syncthreads();
    fft256_tw(sre, sim, tw, t, true);     // unscaled inverse

    g_fre[base + t * NKX]         = sre[t];
    g_fim[base + t * NKX]         = sim[t];
    g_fre[base + (t + 128) * NKX] = sre[t + 128];
    g_fim[base + (t + 128) * NKX] = sim[t + 128];
}

// 4) row-wise inverse rfft (Hermitian reconstruct) -> d_out, scale 1/65536
__global__ void __launch_bounds__(128) k_irfft_row(float* __restrict__ out) {
    __shared__ float sre[256], sim[256];
    __shared__ float2 tw[128];
    int t = threadIdx.x;
    init_tw(tw, t);
    int row = blockIdx.x;                 // b*256 + y
    const float* dre = &g_fre[row * NKX];
    const float* dim = &g_fim[row * NKX];
    #pragma unroll
    for (int i = t; i < 256; i += 128) {
        int k = brev8(i);
        float re, im;
        if (k <= 128) { re = dre[k];        im =  dim[k]; }
        else          { re = dre[256 - k];  im = -dim[256 - k]; }
        sre[i] = re;  sim[i] = im;
    }
    __syncthreads();
    fft256_tw(sre, sim, tw, t, true);
    const float s = 1.0f / 65536.0f;      // 1/(256*256)
    out[row * XS_ + t]       = sre[t]       * s;
    out[row * XS_ + t + 128] = sre[t + 128] * s;
}

// ============================================================
extern "C" void kernel_launch(void* const* d_in, const int* in_sizes, int n_in,
                              void* d_out, int out_size) {
    const float* rows   = (const float*)d_in[0];
    const float* shifts = (const float*)d_in[1];
    const float* latent = (const float*)d_in[2];
    const float* coords = (const float*)d_in[3];
    const float* values = (const float*)d_in[4];
    const float* W0     = (const float*)d_in[5];
    const float* b0     = (const float*)d_in[6];
    const float* W1     = (const float*)d_in[7];
    const float* b1     = (const float*)d_in[8];
    const float* W2     = (const float*)d_in[9];
    const float* b2     = (const float*)d_in[10];
    const float* W3     = (const float*)d_in[11];
    const float* b3     = (const float*)d_in[12];
    const float* Wd     = (const float*)d_in[13];
    const float* bd     = (const float*)d_in[14];
    const float* ctf    = (const float*)d_in[15];
    float* out = (float*)d_out;

    const int IMG = BB * XS_ * XS_;
    k_zero_prep<<<(IMG + 255) / 256, 256>>>(rows, shifts, latent,
                                            W0, b0, W1, b1, W2, b2, W3, b3);
    k_scatter<<<(NN + 255) / 256, 256>>>(coords, values, Wd, bd);
    k_rfft_row<<<BB * XS_, 128>>>();
    k_col_ctf<<<BB * NKX, 128>>>(ctf);
    k_irfft_row<<<BB * XS_, 128>>>(out);
}

// round 7
// speedup vs baseline: 1.1147x; 1.1147x over previous
#include <cuda_runtime.h>
#include <cstdint>

#define BB   16
#define XS_  256
#define NN   500000
#define LATD 8
#define NKX  129   // XS/2 + 1
#define TILE 16
#define TP   17    // padded tile width
#define NTILE 9    // ceil(129/16)

// ---- static scratch (no allocs allowed) ----
__device__ float g_img [BB * XS_ * XS_];
__device__ float g_tmp [BB * XS_ * XS_];
__device__ float g_fre [BB * XS_ * NKX];
__device__ float g_fim [BB * XS_ * NKX];
__device__ float g_h   [BB * LATD];
__device__ float g_pose[BB * 8];

// ============================================================
// 0) zero image + pose/MLP prep
// ============================================================
__global__ void k_zero_prep(const float* __restrict__ rows,
                            const float* __restrict__ shifts,
                            const float* __restrict__ latent,
                            const float* __restrict__ W0, const float* __restrict__ b0,
                            const float* __restrict__ W1, const float* __restrict__ b1,
                            const float* __restrict__ W2, const float* __restrict__ b2,
                            const float* __restrict__ W3, const float* __restrict__ b3) {
    int i = blockIdx.x * blockDim.x + threadIdx.x;
    if (i < BB * XS_ * XS_) g_img[i] = 0.0f;

    if (blockIdx.x == 0 && threadIdx.x < BB) {
        int b = threadIdx.x;
        float rot = rows[b*3+0], tilt = rows[b*3+1], psi = rows[b*3+2];
        float ca = cosf(rot),  sa = sinf(rot);
        float cb = cosf(tilt), sb = sinf(tilt);
        float cg = cosf(psi),  sg = sinf(psi);

        float cgcb  = __fmul_rn(cg, cb);
        float nsgcb = __fmul_rn(-sg, cb);

        float r00 = __fsub_rn(__fmul_rn(cgcb, ca), __fmul_rn(sg, sa));
        float r01 = __fadd_rn(__fmul_rn(cgcb, sa), __fmul_rn(sg, ca));
        float r02 = -__fmul_rn(cg, sb);
        float r10 = __fsub_rn(__fmul_rn(nsgcb, ca), __fmul_rn(cg, sa));
        float r11 = __fadd_rn(__fmul_rn(nsgcb, sa), __fmul_rn(cg, ca));
        float r12 = __fmul_rn(sg, sb);

        g_pose[b*8+0] = r00;
        g_pose[b*8+1] = r01;
        g_pose[b*8+2] = r02;
        g_pose[b*8+3] = r10;
        g_pose[b*8+4] = r11;
        g_pose[b*8+5] = r12;
        g_pose[b*8+6] = shifts[b*2+0];
        g_pose[b*8+7] = shifts[b*2+1];

        float lat[LATD];
        #pragma unroll
        for (int ii = 0; ii < LATD; ii++) lat[ii] = latent[b*LATD+ii];

        float h[LATD], z[LATD];
        #pragma unroll
        for (int j = 0; j < LATD; j++) {
            float acc = 0.0f;
            #pragma unroll
            for (int ii = 0; ii < LATD; ii++) acc = fmaf(lat[ii], W0[ii*LATD+j], acc);
            acc = __fadd_rn(acc, b0[j]);
            h[j] = sinf(__fmul_rn(30.0f, acc));
        }
        const float* Ws[3] = {W1, W2, W3};
        const float* bs[3] = {b1, b2, b3};
        for (int L = 0; L < 3; L++) {
            #pragma unroll
            for (int j = 0; j < LATD; j++) {
                float acc = 0.0f;
                #pragma unroll
                for (int ii = 0; ii < LATD; ii++) acc = fmaf(h[ii], Ws[L][ii*LATD+j], acc);
                acc = __fadd_rn(acc, bs[L][j]);
                z[j] = sinf(acc);
            }
            #pragma unroll
            for (int j = 0; j < LATD; j++) h[j] = __fadd_rn(h[j], z[j]);
        }
        #pragma unroll
        for (int j = 0; j < LATD; j++) g_h[b*LATD+j] = h[j];
    }
}

// ============================================================
// 1) rotation + decode + scatter-add (bit-identical arithmetic)
// ============================================================
__global__ void __launch_bounds__(256)
k_scatter(const float* __restrict__ coords,
          const float* __restrict__ values,
          const float* __restrict__ Wd,
          const float* __restrict__ bd) {
    __shared__ float4 sh[BB * 2];   // h packed
    __shared__ float4 sp[BB * 2];   // pose packed
    int t = threadIdx.x;
    if (t < BB * 2) {
        const float4* gh = (const float4*)g_h;
        const float4* gp = (const float4*)g_pose;
        sh[t] = gh[t];
        sp[t] = gp[t];
    }
    __syncthreads();

    int n = blockIdx.x * blockDim.x + t;
    if (n >= NN) return;

    float x  = coords[3*n+0];
    float y  = coords[3*n+1];
    float zc = coords[3*n+2];
    float w[LATD];
    #pragma unroll
    for (int l = 0; l < LATD; l++) w[l] = Wd[l*NN + n];
    float vn  = values[n];
    float bdn = bd[n];

    #pragma unroll
    for (int b = 0; b < BB; b++) {
        float4 pa = sp[b*2+0];     // r00 r01 r02 r10
        float4 pb = sp[b*2+1];     // r11 r12 sx  sy
        float dx = fmaf(pa.x, x, 0.0f);
        dx = fmaf(pa.y, y,  dx);
        dx = fmaf(pa.z, zc, dx);
        float dy = fmaf(pa.w, x, 0.0f);
        dy = fmaf(pb.x, y,  dy);
        dy = fmaf(pb.y, zc, dy);
        float pxf = rintf(__fadd_rn(__fadd_rn(dx, pb.z), 128.0f));
        float pyf = rintf(__fadd_rn(__fadd_rn(dy, pb.w), 128.0f));
        pxf = fminf(fmaxf(pxf, 0.0f), 255.0f);
        pyf = fminf(fmaxf(pyf, 0.0f), 255.0f);
        int px = (int)pxf;
        int py = (int)pyf;

        float4 h0 = sh[b*2+0];
        float4 h1 = sh[b*2+1];
        float acc = 0.0f;
        acc = fmaf(h0.x, w[0], acc);
        acc = fmaf(h0.y, w[1], acc);
        acc = fmaf(h0.z, w[2], acc);
        acc = fmaf(h0.w, w[3], acc);
        acc = fmaf(h1.x, w[4], acc);
        acc = fmaf(h1.y, w[5], acc);
        acc = fmaf(h1.z, w[6], acc);
        acc = fmaf(h1.w, w[7], acc);
        float v = __fadd_rn(vn, __fadd_rn(acc, bdn));
        atomicAdd(&g_img[(b << 16) + (py << 8) + px], v);
    }
}

// ============================================================
// 2) separable Gaussian blur (identical to 96.3us version)
// ============================================================
__device__ __forceinline__ float gwt(int d) {
    const float w0 = 0.00443305f;   // |d|=3
    const float w1 = 0.05400558f;   // |d|=2
    const float w2 = 0.24203623f;   // |d|=1
    const float w3 = 0.39905033f;   // d=0
    int a = d < 0 ? -d : d;
    return a == 0 ? w3 : (a == 1 ? w2 : (a == 2 ? w1 : w0));
}

__global__ void k_blur_v() {   // along y (H), g_img -> g_tmp
    int i = blockIdx.x * blockDim.x + threadIdx.x;
    if (i >= BB * XS_ * XS_) return;
    int x = i & 255;
    int y = (i >> 8) & 255;
    int b = i >> 16;
    float acc = 0.0f;
    #pragma unroll
    for (int d = -3; d <= 3; d++) {
        int yy = y + d;
        if (yy >= 0 && yy < XS_)
            acc += gwt(d) * g_img[(b*XS_ + yy)*XS_ + x];
    }
    g_tmp[i] = acc;
}

__global__ void k_blur_h() {   // along x (W), g_tmp -> g_img
    int i = blockIdx.x * blockDim.x + threadIdx.x;
    if (i >= BB * XS_ * XS_) return;
    int x = i & 255;
    float acc = 0.0f;
    #pragma unroll
    for (int d = -3; d <= 3; d++) {
        int xx = x + d;
        if (xx >= 0 && xx < XS_)
            acc += gwt(d) * g_tmp[i - x + xx];
    }
    g_img[i] = acc;
}

// ============================================================
// FFT helpers
// ============================================================
__device__ __forceinline__ int brev8(int i) { return (int)(__brev((unsigned)i) >> 24); }

__device__ __forceinline__ void init_tw(float2* tw, int t) {
    float s, c;
    sincospif((float)t * (1.0f / 128.0f), &s, &c);
    tw[t] = make_float2(c, -s);   // e^{-2pi i t/256}
}

// single-column FFT (128 threads); input bit-reversed, output natural
__device__ __forceinline__ void fft256_tw(float* sre, float* sim,
                                          const float2* tw, int t, bool inv) {
    #pragma unroll
    for (int s = 1; s <= 8; s++) {
        int half = 1 << (s - 1);
        int len  = half << 1;
        int grp = t >> (s - 1);
        int j   = t & (half - 1);
        int i0  = grp * len + j;
        int i1  = i0 + half;
        float2 w = tw[j << (8 - s)];
        float wr = w.x;
        float wi = inv ? -w.y : w.y;
        float xr = sre[i1], xi = sim[i1];
        float vr = xr*wr - xi*wi;
        float vi = xr*wi + xi*wr;
        float ur = sre[i0], ui = sim[i0];
        sre[i0] = ur + vr;  sim[i0] = ui + vi;
        sre[i1] = ur - vr;  sim[i1] = ui - vi;
        __syncthreads();
    }
}

// 16-column batched FFT in [y][c] tile (256 threads, TP-padded rows)
__device__ __forceinline__ void fft256_cols(float* re, float* im,
                                            const float2* tw, int tid, bool inv) {
    #pragma unroll
    for (int s = 1; s <= 8; s++) {
        int half = 1 << (s - 1);
        int len  = half << 1;
        #pragma unroll
        for (int it = 0; it < 8; it++) {
            int c  = tid & 15;
            int bf = it * 16 + (tid >> 4);      // 0..127
            int j   = bf & (half - 1);
            int grp = bf >> (s - 1);
            int i0  = grp * len + j;
            int i1  = i0 + half;
            float2 w = tw[j << (8 - s)];
            float wr = w.x;
            float wi = inv ? -w.y : w.y;
            float xr = re[i1*TP + c], xi = im[i1*TP + c];
            float vr = xr*wr - xi*wi;
            float vi = xr*wi + xi*wr;
            float ur = re[i0*TP + c], ui = im[i0*TP + c];
            re[i0*TP + c] = ur + vr;  im[i0*TP + c] = ui + vi;
            re[i1*TP + c] = ur - vr;  im[i1*TP + c] = ui - vi;
        }
        __syncthreads();
    }
}

// 3) row-wise rfft: g_img rows -> g_fre/g_fim [row][0..128]
__global__ void __launch_bounds__(128) k_rfft_row() {
    __shared__ float sre[256], sim[256];
    __shared__ float2 tw[128];
    int t = threadIdx.x;
    init_tw(tw, t);
    int row = blockIdx.x;                 // b*256 + y
    const float* src = &g_img[row * XS_];
    sre[t]       = src[brev8(t)];        sim[t]       = 0.0f;
    sre[t + 128] = src[brev8(t + 128)];  sim[t + 128] = 0.0f;
    __syncthreads();
    fft256_tw(sre, sim, tw, t, false);
    float* dre = &g_fre[row * NKX];
    float* dim = &g_fim[row * NKX];
    dre[t] = sre[t];  dim[t] = sim[t];
    if (t == 0) { dre[128] = sre[128]; dim[128] = sim[128]; }
}

// 4) column FFT over y + CTF + inverse column FFT, tiled 16 kx per block.
//    Coalesced: 16 consecutive kx per 16 lanes (64B segments).
__global__ void __launch_bounds__(256) k_col_ctf(const float* __restrict__ ctf) {
    __shared__ float Bre[256 * TP], Bim[256 * TP];
    __shared__ float2 tw[128];
    int tid = threadIdx.x;
    if (tid < 128) init_tw(tw, tid);

    int bt   = blockIdx.x;
    int b    = bt / NTILE;
    int tile = bt % NTILE;
    int kx0  = tile * TILE;
    int c    = tid & 15;
    int y0   = tid >> 4;
    int base = b * XS_ * NKX;
    bool valid = (kx0 + c) < NKX;
    int gofs = base + kx0 + c;

    // load columns, write into bit-reversed y positions
    #pragma unroll
    for (int i = 0; i < 16; i++) {
        int y = i * 16 + y0;
        float re = 0.0f, im = 0.0f;
        if (valid) {
            re = g_fre[gofs + y * NKX];
            im = g_fim[gofs + y * NKX];
        }
        int ry = brev8(y);
        Bre[ry * TP + c] = re;
        Bim[ry * TP + c] = im;
    }
    __syncthreads();

    fft256_cols(Bre, Bim, tw, tid, false);

    // CTF multiply (natural ky order) into registers
    float vr[16], vi[16];
    #pragma unroll
    for (int i = 0; i < 16; i++) {
        int y = i * 16 + y0;
        float cv = valid ? ctf[gofs + y * NKX] : 0.0f;
        vr[i] = Bre[y * TP + c] * cv;
        vi[i] = Bim[y * TP + c] * cv;
    }
    __syncthreads();
    // scatter back bit-reversed for the inverse pass
    #pragma unroll
    for (int i = 0; i < 16; i++) {
        int y = i * 16 + y0;
        int ry = brev8(y);
        Bre[ry * TP + c] = vr[i];
        Bim[ry * TP + c] = vi[i];
    }
    __syncthreads();

    fft256_cols(Bre, Bim, tw, tid, true);   // unscaled inverse

    #pragma unroll
    for (int i = 0; i < 16; i++) {
        int y = i * 16 + y0;
        if (valid) {
            g_fre[gofs + y * NKX] = Bre[y * TP + c];
            g_fim[gofs + y * NKX] = Bim[y * TP + c];
        }
    }
}

// 5) row-wise inverse rfft (Hermitian reconstruct) -> d_out, scale 1/65536
__global__ void __launch_bounds__(128) k_irfft_row(float* __restrict__ out) {
    __shared__ float sre[256], sim[256];
    __shared__ float2 tw[128];
    int t = threadIdx.x;
    init_tw(tw, t);
    int row = blockIdx.x;                 // b*256 + y
    const float* dre = &g_fre[row * NKX];
    const float* dim = &g_fim[row * NKX];
    #pragma unroll
    for (int i = t; i < 256; i += 128) {
        int k = brev8(i);
        float re, im;
        if (k <= 128) { re = dre[k];        im =  dim[k]; }
        else          { re = dre[256 - k];  im = -dim[256 - k]; }
        sre[i] = re;  sim[i] = im;
    }
    __syncthreads();
    fft256_tw(sre, sim, tw, t, true);
    const float s = 1.0f / 65536.0f;      // 1/(256*256)
    out[row * XS_ + t]       = sre[t]       * s;
    out[row * XS_ + t + 128] = sre[t + 128] * s;
}

// ============================================================
extern "C" void kernel_launch(void* const* d_in, const int* in_sizes, int n_in,
                              void* d_out, int out_size) {
    const float* rows   = (const float*)d_in[0];
    const float* shifts = (const float*)d_in[1];
    const float* latent = (const float*)d_in[2];
    const float* coords = (const float*)d_in[3];
    const float* values = (const float*)d_in[4];
    const float* W0     = (const float*)d_in[5];
    const float* b0     = (const float*)d_in[6];
    const float* W1     = (const float*)d_in[7];
    const float* b1     = (const float*)d_in[8];
    const float* W2     = (const float*)d_in[9];
    const float* b2     = (const float*)d_in[10];
    const float* W3     = (const float*)d_in[11];
    const float* b3     = (const float*)d_in[12];
    const float* Wd     = (const float*)d_in[13];
    const float* bd     = (const float*)d_in[14];
    const float* ctf    = (const float*)d_in[15];
    float* out = (float*)d_out;

    const int IMG = BB * XS_ * XS_;
    k_zero_prep<<<(IMG + 255) / 256, 256>>>(rows, shifts, latent,
                                            W0, b0, W1, b1, W2, b2, W3, b3);
    k_scatter<<<(NN + 255) / 256, 256>>>(coords, values, Wd, bd);
    k_blur_v<<<(IMG + 255) / 256, 256>>>();
    k_blur_h<<<(IMG + 255) / 256, 256>>>();
    k_rfft_row<<<BB * XS_, 128>>>();
    k_col_ctf<<<BB * NTILE, 256>>>(ctf);
    k_irfft_row<<<BB * XS_, 128>>>(out);
}

// round 10
// speedup vs baseline: 1.1493x; 1.0311x over previous
#include <cuda_runtime.h>
#include <cstdint>

#define BB   16
#define XS_  256
#define NN   500000
#define LATD 8
#define NKX  129   // XS/2 + 1

// ---- static scratch (no allocs allowed) ----
__device__ float  g_img [BB * XS_ * XS_];
__device__ float  g_tmp [BB * XS_ * XS_];
__device__ float2 g_fc  [BB * NKX * XS_];   // kx-major: [(b*NKX+kx)*XS_ + y]
__device__ float  g_ctfT[BB * NKX * XS_];   // transposed ctf, same layout
__device__ float  g_h   [BB * LATD];
__device__ float  g_pose[BB * 8];

// ============================================================
// 0) zero image + pose/MLP prep
// ============================================================
__global__ void k_zero_prep(const float* __restrict__ rows,
                            const float* __restrict__ shifts,
                            const float* __restrict__ latent,
                            const float* __restrict__ W0, const float* __restrict__ b0,
                            const float* __restrict__ W1, const float* __restrict__ b1,
                            const float* __restrict__ W2, const float* __restrict__ b2,
                            const float* __restrict__ W3, const float* __restrict__ b3) {
    int i = blockIdx.x * blockDim.x + threadIdx.x;
    if (i < BB * XS_ * XS_) g_img[i] = 0.0f;

    if (blockIdx.x == 0 && threadIdx.x < BB) {
        int b = threadIdx.x;
        float rot = rows[b*3+0], tilt = rows[b*3+1], psi = rows[b*3+2];
        float ca = cosf(rot),  sa = sinf(rot);
        float cb = cosf(tilt), sb = sinf(tilt);
        float cg = cosf(psi),  sg = sinf(psi);

        float cgcb  = __fmul_rn(cg, cb);
        float nsgcb = __fmul_rn(-sg, cb);

        float r00 = __fsub_rn(__fmul_rn(cgcb, ca), __fmul_rn(sg, sa));
        float r01 = __fadd_rn(__fmul_rn(cgcb, sa), __fmul_rn(sg, ca));
        float r02 = -__fmul_rn(cg, sb);
        float r10 = __fsub_rn(__fmul_rn(nsgcb, ca), __fmul_rn(cg, sa));
        float r11 = __fadd_rn(__fmul_rn(nsgcb, sa), __fmul_rn(cg, ca));
        float r12 = __fmul_rn(sg, sb);

        g_pose[b*8+0] = r00;
        g_pose[b*8+1] = r01;
        g_pose[b*8+2] = r02;
        g_pose[b*8+3] = r10;
        g_pose[b*8+4] = r11;
        g_pose[b*8+5] = r12;
        g_pose[b*8+6] = shifts[b*2+0];
        g_pose[b*8+7] = shifts[b*2+1];

        float lat[LATD];
        #pragma unroll
        for (int ii = 0; ii < LATD; ii++) lat[ii] = latent[b*LATD+ii];

        float h[LATD], z[LATD];
        #pragma unroll
        for (int j = 0; j < LATD; j++) {
            float acc = 0.0f;
            #pragma unroll
            for (int ii = 0; ii < LATD; ii++) acc = fmaf(lat[ii], W0[ii*LATD+j], acc);
            acc = __fadd_rn(acc, b0[j]);
            h[j] = sinf(__fmul_rn(30.0f, acc));
        }
        const float* Ws[3] = {W1, W2, W3};
        const float* bs[3] = {b1, b2, b3};
        for (int L = 0; L < 3; L++) {
            #pragma unroll
            for (int j = 0; j < LATD; j++) {
                float acc = 0.0f;
                #pragma unroll
                for (int ii = 0; ii < LATD; ii++) acc = fmaf(h[ii], Ws[L][ii*LATD+j], acc);
                acc = __fadd_rn(acc, bs[L][j]);
                z[j] = sinf(acc);
            }
            #pragma unroll
            for (int j = 0; j < LATD; j++) h[j] = __fadd_rn(h[j], z[j]);
        }
        #pragma unroll
        for (int j = 0; j < LATD; j++) g_h[b*LATD+j] = h[j];
    }
}

// ============================================================
// 0b) transpose CTF: ctf[b][y][kx] -> g_ctfT[(b*NKX+kx)*XS_ + y]
//     grid (5, 8, 16), block (32, 8)
// ============================================================
__global__ void k_ctfT(const float* __restrict__ ctf) {
    __shared__ float tile[32][33];
    int b   = blockIdx.z;
    int kx0 = blockIdx.x * 32;
    int y0  = blockIdx.y * 32;
    int tx  = threadIdx.x, ty = threadIdx.y;
    #pragma unroll
    for (int yy = ty; yy < 32; yy += 8) {
        int kx = kx0 + tx;
        tile[yy][tx] = (kx < NKX) ? ctf[(b*XS_ + y0 + yy)*NKX + kx] : 0.0f;
    }
    __syncthreads();
    #pragma unroll
    for (int a = ty; a < 32; a += 8) {
        int kx = kx0 + a;
        if (kx < NKX) g_ctfT[(b*NKX + kx)*XS_ + y0 + tx] = tile[tx][a];
    }
}

// ============================================================
// 1) rotation + decode + scatter-add (bit-identical arithmetic)
// ============================================================
__global__ void __launch_bounds__(256)
k_scatter(const float* __restrict__ coords,
          const float* __restrict__ values,
          const float* __restrict__ Wd,
          const float* __restrict__ bd) {
    __shared__ float4 sh[BB * 2];   // h packed
    __shared__ float4 sp[BB * 2];   // pose packed
    int t = threadIdx.x;
    if (t < BB * 2) {
        const float4* gh = (const float4*)g_h;
        const float4* gp = (const float4*)g_pose;
        sh[t] = gh[t];
        sp[t] = gp[t];
    }
    __syncthreads();

    int n = blockIdx.x * blockDim.x + t;
    if (n >= NN) return;

    float x  = coords[3*n+0];
    float y  = coords[3*n+1];
    float zc = coords[3*n+2];
    float w[LATD];
    #pragma unroll
    for (int l = 0; l < LATD; l++) w[l] = Wd[l*NN + n];
    float vn  = values[n];
    float bdn = bd[n];

    #pragma unroll
    for (int b = 0; b < BB; b++) {
        float4 pa = sp[b*2+0];     // r00 r01 r02 r10
        float4 pb = sp[b*2+1];     // r11 r12 sx  sy
        float dx = fmaf(pa.x, x, 0.0f);
        dx = fmaf(pa.y, y,  dx);
        dx = fmaf(pa.z, zc, dx);
        float dy = fmaf(pa.w, x, 0.0f);
        dy = fmaf(pb.x, y,  dy);
        dy = fmaf(pb.y, zc, dy);
        float pxf = rintf(__fadd_rn(__fadd_rn(dx, pb.z), 128.0f));
        float pyf = rintf(__fadd_rn(__fadd_rn(dy, pb.w), 128.0f));
        pxf = fminf(fmaxf(pxf, 0.0f), 255.0f);
        pyf = fminf(fmaxf(pyf, 0.0f), 255.0f);
        int px = (int)pxf;
        int py = (int)pyf;

        float4 h0 = sh[b*2+0];
        float4 h1 = sh[b*2+1];
        float acc = 0.0f;
        acc = fmaf(h0.x, w[0], acc);
        acc = fmaf(h0.y, w[1], acc);
        acc = fmaf(h0.z, w[2], acc);
        acc = fmaf(h0.w, w[3], acc);
        acc = fmaf(h1.x, w[4], acc);
        acc = fmaf(h1.y, w[5], acc);
        acc = fmaf(h1.z, w[6], acc);
        acc = fmaf(h1.w, w[7], acc);
        float v = __fadd_rn(vn, __fadd_rn(acc, bdn));
        atomicAdd(&g_img[(b << 16) + (py << 8) + px], v);
    }
}

// ============================================================
// 2) separable Gaussian blur (bit-identical to 96.3us version)
// ============================================================
__device__ __forceinline__ float gwt(int d) {
    const float w0 = 0.00443305f;   // |d|=3
    const float w1 = 0.05400558f;   // |d|=2
    const float w2 = 0.24203623f;   // |d|=1
    const float w3 = 0.39905033f;   // d=0
    int a = d < 0 ? -d : d;
    return a == 0 ? w3 : (a == 1 ? w2 : (a == 2 ? w1 : w0));
}

__global__ void k_blur_v() {   // along y (H), g_img -> g_tmp
    int i = blockIdx.x * blockDim.x + threadIdx.x;
    if (i >= BB * XS_ * XS_) return;
    int x = i & 255;
    int y = (i >> 8) & 255;
    int b = i >> 16;
    float acc = 0.0f;
    #pragma unroll
    for (int d = -3; d <= 3; d++) {
        int yy = y + d;
        if (yy >= 0 && yy < XS_)
            acc += gwt(d) * g_img[(b*XS_ + yy)*XS_ + x];
    }
    g_tmp[i] = acc;
}

__global__ void k_blur_h() {   // along x (W), g_tmp -> g_img
    int i = blockIdx.x * blockDim.x + threadIdx.x;
    if (i >= BB * XS_ * XS_) return;
    int x = i & 255;
    float acc = 0.0f;
    #pragma unroll
    for (int d = -3; d <= 3; d++) {
        int xx = x + d;
        if (xx >= 0 && xx < XS_)
            acc += gwt(d) * g_tmp[i - x + xx];
    }
    g_img[i] = acc;
}

// ============================================================
// FFT helpers (arithmetic identical to passing versions)
// ============================================================
__device__ __forceinline__ int brev8(int i) { return (int)(__brev((unsigned)i) >> 24); }

__device__ __forceinline__ void init_tw(float2* tw, int t) {
    float s, c;
    sincospif((float)t * (1.0f / 128.0f), &s, &c);
    tw[t] = make_float2(c, -s);   // e^{-2pi i t/256}
}

__device__ __forceinline__ void fft256_tw(float* sre, float* sim,
                                          const float2* tw, int t, bool inv) {
    #pragma unroll
    for (int s = 1; s <= 8; s++) {
        int half = 1 << (s - 1);
        int len  = half << 1;
        int grp = t >> (s - 1);
        int j   = t & (half - 1);
        int i0  = grp * len + j;
        int i1  = i0 + half;
        float2 w = tw[j << (8 - s)];
        float wr = w.x;
        float wi = inv ? -w.y : w.y;
        float xr = sre[i1], xi = sim[i1];
        float vr = xr*wr - xi*wi;
        float vi = xr*wi + xi*wr;
        float ur = sre[i0], ui = sim[i0];
        sre[i0] = ur + vr;  sim[i0] = ui + vi;
        sre[i1] = ur - vr;  sim[i1] = ui - vi;
        __syncthreads();
    }
}

// 3) row-wise rfft: g_img rows -> g_fc (kx-major)
__global__ void __launch_bounds__(128) k_rfft_row() {
    __shared__ float sre[256], sim[256];
    __shared__ float2 tw[128];
    int t = threadIdx.x;
    init_tw(tw, t);
    int row = blockIdx.x;                 // b*256 + y
    int b = row >> 8;
    int y = row & 255;
    const float* src = &g_img[row * XS_];
    sre[t]       = src[brev8(t)];        sim[t]       = 0.0f;
    sre[t + 128] = src[brev8(t + 128)];  sim[t + 128] = 0.0f;
    __syncthreads();
    fft256_tw(sre, sim, tw, t, false);
    float2* dst = &g_fc[(b * NKX) * XS_ + y];   // + kx*XS_
    dst[t * XS_] = make_float2(sre[t], sim[t]);
    if (t == 0) dst[128 * XS_] = make_float2(sre[128], sim[128]);
}

// 4) column FFT over y + CTF + inverse column FFT; block per (b,kx).
//    All global accesses fully contiguous (kx-major layout).
__global__ void __launch_bounds__(128) k_col_ctf() {
    __shared__ float sre[256], sim[256];
    __shared__ float2 tw[128];
    int t = threadIdx.x;
    init_tw(tw, t);
    int col = blockIdx.x;                 // b*NKX + kx
    float2* fc = &g_fc[col * XS_];
    const float* ct = &g_ctfT[col * XS_];

    float2 a0 = fc[t];
    float2 a1 = fc[t + 128];
    int r0 = brev8(t), r1 = brev8(t + 128);
    sre[r0] = a0.x;  sim[r0] = a0.y;
    sre[r1] = a1.x;  sim[r1] = a1.y;
    __syncthreads();
    fft256_tw(sre, sim, tw, t, false);

    float c0 = ct[t];
    float c1 = ct[t + 128];
    float ar = sre[t]       * c0, ai = sim[t]       * c0;
    float br = sre[t + 128] * c1, bi = sim[t + 128] * c1;
    __syncthreads();
    sre[r0] = ar;  sim[r0] = ai;
    sre[r1] = br;  sim[r1] = bi;
    __syncthreads();
    fft256_tw(sre, sim, tw, t, true);     // unscaled inverse

    fc[t]       = make_float2(sre[t],       sim[t]);
    fc[t + 128] = make_float2(sre[t + 128], sim[t + 128]);
}

// 5) row-wise inverse rfft (Hermitian reconstruct) -> d_out, scale 1/65536
__global__ void __launch_bounds__(128) k_irfft_row(float* __restrict__ out) {
    __shared__ float sre[256], sim[256];
    __shared__ float2 tw[128];
    int t = threadIdx.x;
    init_tw(tw, t);
    int row = blockIdx.x;                 // b*256 + y
    int b = row >> 8;
    int y = row & 255;
    const float2* src = &g_fc[(b * NKX) * XS_ + y];   // + kx*XS_
    #pragma unroll
    for (int i = t; i < 256; i += 128) {
        int k = brev8(i);
        float2 v;
        if (k <= 128) { v = src[k * XS_]; }
        else          { v = src[(256 - k) * XS_];  v.y = -v.y; }
        sre[i] = v.x;  sim[i] = v.y;
    }
    __syncthreads();
    fft256_tw(sre, sim, tw, t, true);
    const float s = 1.0f / 65536.0f;      // 1/(256*256)
    out[row * XS_ + t]       = sre[t]       * s;
    out[row * XS_ + t + 128] = sre[t + 128] * s;
}

// ============================================================
extern "C" void kernel_launch(void* const* d_in, const int* in_sizes, int n_in,
                              void* d_out, int out_size) {
    const float* rows   = (const float*)d_in[0];
    const float* shifts = (const float*)d_in[1];
    const float* latent = (const float*)d_in[2];
    const float* coords = (const float*)d_in[3];
    const float* values = (const float*)d_in[4];
    const float* W0     = (const float*)d_in[5];
    const float* b0     = (const float*)d_in[6];
    const float* W1     = (const float*)d_in[7];
    const float* b1     = (const float*)d_in[8];
    const float* W2     = (const float*)d_in[9];
    const float* b2     = (const float*)d_in[10];
    const float* W3     = (const float*)d_in[11];
    const float* b3     = (const float*)d_in[12];
    const float* Wd     = (const float*)d_in[13];
    const float* bd     = (const float*)d_in[14];
    const float* ctf    = (const float*)d_in[15];
    float* out = (float*)d_out;

    const int IMG = BB * XS_ * XS_;
    k_zero_prep<<<(IMG + 255) / 256, 256>>>(rows, shifts, latent,
                                            W0, b0, W1, b1, W2, b2, W3, b3);
    {
        dim3 g(5, 8, BB), blk(32, 8);
        k_ctfT<<<g, blk>>>(ctf);
    }
    k_scatter<<<(NN + 255) / 256, 256>>>(coords, values, Wd, bd);
    k_blur_v<<<(IMG + 255) / 256, 256>>>();
    k_blur_h<<<(IMG + 255) / 256, 256>>>();
    k_rfft_row<<<BB * XS_, 128>>>();
    k_col_ctf<<<BB * NKX, 128>>>();
    k_irfft_row<<<BB * XS_, 128>>>(out);
}

// round 14
// speedup vs baseline: 1.3336x; 1.1603x over previous
#include <cuda_runtime.h>
#include <cstdint>

#define BB   16
#define XS_  256
#define NN   500000
#define LATD 8
#define NKX  129   // XS/2 + 1
#define SROW 257   // padded FFT row stride (floats)

// ---- static scratch (no allocs allowed) ----
__device__ float  g_img [BB * XS_ * XS_];
__device__ float2 g_fc  [BB * NKX * XS_];   // kx-major: [(b*NKX+kx)*XS_ + y]
__device__ float  g_ctfT[BB * NKX * XS_];   // transposed ctf, same layout
__device__ float  g_h   [BB * LATD];
__device__ float  g_pose[BB * 8];

// ============================================================
// 0) zero image + pose/MLP prep
// ============================================================
__global__ void k_zero_prep(const float* __restrict__ rows,
                            const float* __restrict__ shifts,
                            const float* __restrict__ latent,
                            const float* __restrict__ W0, const float* __restrict__ b0,
                            const float* __restrict__ W1, const float* __restrict__ b1,
                            const float* __restrict__ W2, const float* __restrict__ b2,
                            const float* __restrict__ W3, const float* __restrict__ b3) {
    int i = blockIdx.x * blockDim.x + threadIdx.x;
    if (i < BB * XS_ * XS_) g_img[i] = 0.0f;

    if (blockIdx.x == 0 && threadIdx.x < BB) {
        int b = threadIdx.x;
        float rot = rows[b*3+0], tilt = rows[b*3+1], psi = rows[b*3+2];
        float ca = cosf(rot),  sa = sinf(rot);
        float cb = cosf(tilt), sb = sinf(tilt);
        float cg = cosf(psi),  sg = sinf(psi);

        float cgcb  = __fmul_rn(cg, cb);
        float nsgcb = __fmul_rn(-sg, cb);

        float r00 = __fsub_rn(__fmul_rn(cgcb, ca), __fmul_rn(sg, sa));
        float r01 = __fadd_rn(__fmul_rn(cgcb, sa), __fmul_rn(sg, ca));
        float r02 = -__fmul_rn(cg, sb);
        float r10 = __fsub_rn(__fmul_rn(nsgcb, ca), __fmul_rn(cg, sa));
        float r11 = __fadd_rn(__fmul_rn(nsgcb, sa), __fmul_rn(cg, ca));
        float r12 = __fmul_rn(sg, sb);

        g_pose[b*8+0] = r00;
        g_pose[b*8+1] = r01;
        g_pose[b*8+2] = r02;
        g_pose[b*8+3] = r10;
        g_pose[b*8+4] = r11;
        g_pose[b*8+5] = r12;
        g_pose[b*8+6] = shifts[b*2+0];
        g_pose[b*8+7] = shifts[b*2+1];

        float lat[LATD];
        #pragma unroll
        for (int ii = 0; ii < LATD; ii++) lat[ii] = latent[b*LATD+ii];

        float h[LATD], z[LATD];
        #pragma unroll
        for (int j = 0; j < LATD; j++) {
            float acc = 0.0f;
            #pragma unroll
            for (int ii = 0; ii < LATD; ii++) acc = fmaf(lat[ii], W0[ii*LATD+j], acc);
            acc = __fadd_rn(acc, b0[j]);
            h[j] = sinf(__fmul_rn(30.0f, acc));
        }
        const float* Ws[3] = {W1, W2, W3};
        const float* bs[3] = {b1, b2, b3};
        for (int L = 0; L < 3; L++) {
            #pragma unroll
            for (int j = 0; j < LATD; j++) {
                float acc = 0.0f;
                #pragma unroll
                for (int ii = 0; ii < LATD; ii++) acc = fmaf(h[ii], Ws[L][ii*LATD+j], acc);
                acc = __fadd_rn(acc, bs[L][j]);
                z[j] = sinf(acc);
            }
            #pragma unroll
            for (int j = 0; j < LATD; j++) h[j] = __fadd_rn(h[j], z[j]);
        }
        #pragma unroll
        for (int j = 0; j < LATD; j++) g_h[b*LATD+j] = h[j];
    }
}

// ============================================================
// 0b) transpose CTF: ctf[b][y][kx] -> g_ctfT[(b*NKX+kx)*XS_ + y]
// ============================================================
__global__ void k_ctfT(const float* __restrict__ ctf) {
    __shared__ float tile[32][33];
    int b   = blockIdx.z;
    int kx0 = blockIdx.x * 32;
    int y0  = blockIdx.y * 32;
    int tx  = threadIdx.x, ty = threadIdx.y;
    #pragma unroll
    for (int yy = ty; yy < 32; yy += 8) {
        int kx = kx0 + tx;
        tile[yy][tx] = (kx < NKX) ? ctf[(b*XS_ + y0 + yy)*NKX + kx] : 0.0f;
    }
    __syncthreads();
    #pragma unroll
    for (int a = ty; a < 32; a += 8) {
        int kx = kx0 + a;
        if (kx < NKX) g_ctfT[(b*NKX + kx)*XS_ + y0 + tx] = tile[tx][a];
    }
}

// ============================================================
// 1) rotation + decode + scatter-add (bit-identical arithmetic)
// ============================================================
__global__ void __launch_bounds__(256)
k_scatter(const float* __restrict__ coords,
          const float* __restrict__ values,
          const float* __restrict__ Wd,
          const float* __restrict__ bd) {
    __shared__ float4 sh[BB * 2];
    __shared__ float4 sp[BB * 2];
    int t = threadIdx.x;
    if (t < BB * 2) {
        const float4* gh = (const float4*)g_h;
        const float4* gp = (const float4*)g_pose;
        sh[t] = gh[t];
        sp[t] = gp[t];
    }
    __syncthreads();

    int n = blockIdx.x * blockDim.x + t;
    if (n >= NN) return;

    float x  = coords[3*n+0];
    float y  = coords[3*n+1];
    float zc = coords[3*n+2];
    float w[LATD];
    #pragma unroll
    for (int l = 0; l < LATD; l++) w[l] = Wd[l*NN + n];
    float vn  = values[n];
    float bdn = bd[n];

    #pragma unroll
    for (int b = 0; b < BB; b++) {
        float4 pa = sp[b*2+0];
        float4 pb = sp[b*2+1];
        float dx = fmaf(pa.x, x, 0.0f);
        dx = fmaf(pa.y, y,  dx);
        dx = fmaf(pa.z, zc, dx);
        float dy = fmaf(pa.w, x, 0.0f);
        dy = fmaf(pb.x, y,  dy);
        dy = fmaf(pb.y, zc, dy);
        float pxf = rintf(__fadd_rn(__fadd_rn(dx, pb.z), 128.0f));
        float pyf = rintf(__fadd_rn(__fadd_rn(dy, pb.w), 128.0f));
        pxf = fminf(fmaxf(pxf, 0.0f), 255.0f);
        pyf = fminf(fmaxf(pyf, 0.0f), 255.0f);
        int px = (int)pxf;
        int py = (int)pyf;

        float4 h0 = sh[b*2+0];
        float4 h1 = sh[b*2+1];
        float acc = 0.0f;
        acc = fmaf(h0.x, w[0], acc);
        acc = fmaf(h0.y, w[1], acc);
        acc = fmaf(h0.z, w[2], acc);
        acc = fmaf(h0.w, w[3], acc);
        acc = fmaf(h1.x, w[4], acc);
        acc = fmaf(h1.y, w[5], acc);
        acc = fmaf(h1.z, w[6], acc);
        acc = fmaf(h1.w, w[7], acc);
        float v = __fadd_rn(vn, __fadd_rn(acc, bdn));
        atomicAdd(&g_img[(b << 16) + (py << 8) + px], v);
    }
}

// ============================================================
// helpers
// ============================================================
__device__ __forceinline__ float gwt(int d) {
    const float w0 = 0.00443305f;   // |d|=3
    const float w1 = 0.05400558f;   // |d|=2
    const float w2 = 0.24203623f;   // |d|=1
    const float w3 = 0.39905033f;   // d=0
    int a = d < 0 ? -d : d;
    return a == 0 ? w3 : (a == 1 ? w2 : (a == 2 ? w1 : w0));
}

__device__ __forceinline__ int brev8(int i) { return (int)(__brev((unsigned)i) >> 24); }

__device__ __forceinline__ void init_tw(float2* tw, int t) {
    float s, c;
    sincospif((float)t * (1.0f / 128.0f), &s, &c);
    tw[t] = make_float2(c, -s);   // e^{-2pi i t/256}
}

// batched 16-row FFT; 256 threads; thread = (j = t&127 butterfly, rh = t>>7),
// each handles 8 rows. Butterfly math identical to single-row version.
__device__ __forceinline__ void fft256_b16(float* sre, float* sim,
                                           const float2* tw, int t, bool inv) {
    int j  = t & 127;
    int rh = t >> 7;            // 0 or 1 -> rows rh*8..rh*8+7
    #pragma unroll
    for (int s = 1; s <= 8; s++) {
        int half = 1 << (s - 1);
        int grp = j >> (s - 1);
        int jj  = j & (half - 1);
        int i0  = grp * (half << 1) + jj;
        int i1  = i0 + half;
        float2 w = tw[jj << (8 - s)];
        float wr = w.x;
        float wi = inv ? -w.y : w.y;
        #pragma unroll
        for (int k = 0; k < 8; k++) {
            int r = rh * 8 + k;
            float xr = sre[r*SROW + i1], xi = sim[r*SROW + i1];
            float vr = xr*wr - xi*wi;
            float vi = xr*wi + xi*wr;
            float ur = sre[r*SROW + i0], ui = sim[r*SROW + i0];
            sre[r*SROW + i0] = ur + vr;  sim[r*SROW + i0] = ui + vi;
            sre[r*SROW + i1] = ur - vr;  sim[r*SROW + i1] = ui - vi;
        }
        __syncthreads();
    }
}

// ============================================================
// 2) fused blur_v + blur_h + row rfft, 16 rows per block.
//    grid = BB*16, block = 256. All global accesses coalesced.
// ============================================================
__global__ void __launch_bounds__(256) k_blur_rfft() {
    __shared__ float poolA[22 * 256];        // raw rows; later aliased as sre
    __shared__ float poolB[16 * SROW];       // bv; later aliased as sim
    __shared__ float2 tw[128];
    float* raw = poolA;
    float* sre = poolA;                      // 16*SROW = 4112 <= 5632
    float* bv  = poolB;
    float* sim = poolB;

    int t = threadIdx.x;
    if (t < 128) init_tw(tw, t);
    int blk = blockIdx.x;
    int b  = blk >> 4;
    int y0 = (blk & 15) << 4;

    // load rows y0-3 .. y0+18 (zero outside)
    #pragma unroll
    for (int rr = 0; rr < 22; rr++) {
        int y = y0 + rr - 3;
        raw[rr * 256 + t] = (y >= 0 && y < XS_)
            ? g_img[(((b << 8) + y) << 8) + t] : 0.0f;
    }
    __syncthreads();

    // vertical blur (adding w*0 for out-of-range == original skip)
    float vv[16];
    #pragma unroll
    for (int r = 0; r < 16; r++) {
        float acc = 0.0f;
        #pragma unroll
        for (int d = -3; d <= 3; d++)
            acc += gwt(d) * raw[(r + 3 + d) * 256 + t];
        vv[r] = acc;
    }
    __syncthreads();          // all raw reads done (raw will be overwritten as sre)
    #pragma unroll
    for (int r = 0; r < 16; r++) bv[r * 256 + t] = vv[r];
    __syncthreads();

    // horizontal blur -> FFT input at bit-reversed positions (sre aliases raw)
    int p = brev8(t);
    #pragma unroll
    for (int r = 0; r < 16; r++) {
        float acc = 0.0f;
        #pragma unroll
        for (int d = -3; d <= 3; d++) {
            int xx = t + d;
            if (xx >= 0 && xx < XS_)
                acc += gwt(d) * bv[r * 256 + xx];
        }
        sre[r * SROW + p] = acc;
    }
    __syncthreads();          // all bv reads done (bv will be overwritten as sim)
    #pragma unroll
    for (int r = 0; r < 16; r++) sim[r * SROW + t] = 0.0f;
    __syncthreads();

    fft256_b16(sre, sim, tw, t, false);

    // write kx-major, coalesced: 16 consecutive y per kx
    int yl  = t & 15;
    int kxi = t >> 4;
    float2* dst = &g_fc[(b * NKX) * XS_ + y0 + yl];
    #pragma unroll
    for (int c = 0; c < 8; c++) {
        int kx = c * 16 + kxi;
        dst[kx * XS_] = make_float2(sre[yl * SROW + kx], sim[yl * SROW + kx]);
    }
    if (t < 16)
        dst = &g_fc[(b * NKX + 128) * XS_ + y0 + t],
        *dst = make_float2(sre[t * SROW + 128], sim[t * SROW + 128]);
}

// ============================================================
// 3) column FFT over y + CTF + inverse column FFT; block per (b,kx).
//    Fully contiguous global accesses (kx-major layout).
// ============================================================
__device__ __forceinline__ void fft256_tw(float* sre, float* sim,
                                          const float2* tw, int t, bool inv) {
    #pragma unroll
    for (int s = 1; s <= 8; s++) {
        int half = 1 << (s - 1);
        int len  = half << 1;
        int grp = t >> (s - 1);
        int j   = t & (half - 1);
        int i0  = grp * len + j;
        int i1  = i0 + half;
        float2 w = tw[j << (8 - s)];
        float wr = w.x;
        float wi = inv ? -w.y : w.y;
        float xr = sre[i1], xi = sim[i1];
        float vr = xr*wr - xi*wi;
        float vi = xr*wi + xi*wr;
        float ur = sre[i0], ui = sim[i0];
        sre[i0] = ur + vr;  sim[i0] = ui + vi;
        sre[i1] = ur - vr;  sim[i1] = ui - vi;
        __syncthreads();
    }
}

__global__ void __launch_bounds__(128) k_col_ctf() {
    __shared__ float sre[256], sim[256];
    __shared__ float2 tw[128];
    int t = threadIdx.x;
    init_tw(tw, t);
    int col = blockIdx.x;                 // b*NKX + kx
    float2* fc = &g_fc[col * XS_];
    const float* ct = &g_ctfT[col * XS_];

    float2 a0 = fc[t];
    float2 a1 = fc[t + 128];
    int r0 = brev8(t), r1 = brev8(t + 128);
    sre[r0] = a0.x;  sim[r0] = a0.y;
    sre[r1] = a1.x;  sim[r1] = a1.y;
    __syncthreads();
    fft256_tw(sre, sim, tw, t, false);

    float c0 = ct[t];
    float c1 = ct[t + 128];
    float ar = sre[t]       * c0, ai = sim[t]       * c0;
    float br = sre[t + 128] * c1, bi = sim[t + 128] * c1;
    __syncthreads();
    sre[r0] = ar;  sim[r0] = ai;
    sre[r1] = br;  sim[r1] = bi;
    __syncthreads();
    fft256_tw(sre, sim, tw, t, true);     // unscaled inverse

    fc[t]       = make_float2(sre[t],       sim[t]);
    fc[t + 128] = make_float2(sre[t + 128], sim[t + 128]);
}

// ============================================================
// 4) batched row irfft (Hermitian), 16 rows per block -> d_out.
//    Coalesced kx-major reads, coalesced row writes.
// ============================================================
__global__ void __launch_bounds__(256) k_irfft_b16(float* __restrict__ out) {
    __shared__ float sre[16 * SROW], sim[16 * SROW];
    __shared__ float2 tw[128];
    int t = threadIdx.x;
    if (t < 128) init_tw(tw, t);
    int blk = blockIdx.x;
    int b  = blk >> 4;
    int y0 = (blk & 15) << 4;

    int yl  = t & 15;
    int kxi = t >> 4;
    const float2* src = &g_fc[(b * NKX) * XS_ + y0 + yl];
    __syncthreads();          // tw ready before any use? (tw used after next sync anyway)
    #pragma unroll
    for (int c = 0; c < 8; c++) {
        int kx = c * 16 + kxi;
        float2 v = src[kx * XS_];
        int p1 = brev8(kx);
        sre[yl * SROW + p1] = v.x;
        sim[yl * SROW + p1] = v.y;
        if (kx >= 1) {
            int p2 = brev8(256 - kx);
            sre[yl * SROW + p2] = v.x;
            sim[yl * SROW + p2] = -v.y;
        }
    }
    if (t < 16) {
        float2 v = g_fc[(b * NKX + 128) * XS_ + y0 + t];
        int p1 = brev8(128);
        sre[t * SROW + p1] = v.x;
        sim[t * SROW + p1] = v.y;
    }
    __syncthreads();

    fft256_b16(sre, sim, tw, t, true);

    const float s = 1.0f / 65536.0f;
    #pragma unroll
    for (int r = 0; r < 16; r++)
        out[(((b << 8) + y0 + r) << 8) + t] = sre[r * SROW + t] * s;
}

// ============================================================
extern "C" void kernel_launch(void* const* d_in, const int* in_sizes, int n_in,
                              void* d_out, int out_size) {
    const float* rows   = (const float*)d_in[0];
    const float* shifts = (const float*)d_in[1];
    const float* latent = (const float*)d_in[2];
    const float* coords = (const float*)d_in[3];
    const float* values = (const float*)d_in[4];
    const float* W0     = (const float*)d_in[5];
    const float* b0     = (const float*)d_in[6];
    const float* W1     = (const float*)d_in[7];
    const float* b1     = (const float*)d_in[8];
    const float* W2     = (const float*)d_in[9];
    const float* b2     = (const float*)d_in[10];
    const float* W3     = (const float*)d_in[11];
    const float* b3     = (const float*)d_in[12];
    const float* Wd     = (const float*)d_in[13];
    const float* bd     = (const float*)d_in[14];
    const float* ctf    = (const float*)d_in[15];
    float* out = (float*)d_out;

    const int IMG = BB * XS_ * XS_;
    k_zero_prep<<<(IMG + 255) / 256, 256>>>(rows, shifts, latent,
                                            W0, b0, W1, b1, W2, b2, W3, b3);
    {
        dim3 g(5, 8, BB), blk(32, 8);
        k_ctfT<<<g, blk>>>(ctf);
    }
    k_scatter<<<(NN + 255) / 256, 256>>>(coords, values, Wd, bd);
    k_blur_rfft<<<BB * 16, 256>>>();
    k_col_ctf<<<BB * NKX, 128>>>();
    k_irfft_b16<<<BB * 16, 256>>>(out);
}